// round 2
// baseline (speedup 1.0000x reference)
#include <cuda_runtime.h>
#include <cuda_bf16.h>
#include <math.h>

// ---------------------------------------------------------------------------
// Shapes
// ---------------------------------------------------------------------------
#define NB    32
#define HID   1024
#define TSTEP 63
#define ENCL  64
#define G3    3072

#define DEC_HIDS_ELEMS (NB * TSTEP * HID)               // 2064384
#define ATTS_ELEMS     (NB * ENCL * TSTEP)              // 129024
#define ATT_BASE       DEC_HIDS_ELEMS
#define DECPREV_BASE   (DEC_HIDS_ELEMS + ATTS_ELEMS)

// ---------------------------------------------------------------------------
// Scratch (device globals; no allocation allowed)
// ---------------------------------------------------------------------------
__device__ float g_Wt_dec[1024 * 1024];
__device__ float g_Wt_enc[1024 * 1024];
__device__ float g_Wt_ctx[1024 * 1024];
__device__ float g_Wt_in [1024 * 1024];
__device__ float g_Wt_hh0[1024 * G3];
__device__ float g_Wt_hh1[1024 * G3];
__device__ float g_Wt_ih0[1024 * G3];
__device__ float g_Wt_ih1[1024 * G3];

__device__ float g_enc_proj[NB * ENCL * 1024];   // [(n*64+l)][a]
__device__ float g_emb_merged[TSTEP * NB * 1024];// [(t*32+n)][h]

__device__ float g_h[2 * NB * HID];              // [layer][n][h]
__device__ float g_dec_proj[NB * HID];
__device__ float g_gh0[NB * G3];
__device__ float g_gh1[NB * G3];
__device__ float g_gi [NB * G3];
__device__ float g_merged[NB * HID];
__device__ float g_ctx[NB * HID];

// ---------------------------------------------------------------------------
// init: dec_init -> g_h
// ---------------------------------------------------------------------------
__global__ void init_h_kernel(const float* __restrict__ dec_init) {
    int i = blockIdx.x * 256 + threadIdx.x;
    g_h[i] = dec_init[i];
}

// ---------------------------------------------------------------------------
// Transpose all weights: W[r][k] (K=1024 inner) -> Wt[k][r]
// 16384 blocks of 256 threads, 32x32 tiles
// ---------------------------------------------------------------------------
__global__ void transpose_kernel(const float* __restrict__ W_att_dec,
                                 const float* __restrict__ W_att_enc,
                                 const float* __restrict__ W_ctx,
                                 const float* __restrict__ W_in,
                                 const float* __restrict__ W_hh,
                                 const float* __restrict__ W_ih) {
    __shared__ float s[32][33];
    int b = blockIdx.x;
    const float* in; float* out; int R, loc;
    if (b < 1024)       { in = W_att_dec;        out = g_Wt_dec; R = 1024; loc = b; }
    else if (b < 2048)  { in = W_att_enc;        out = g_Wt_enc; R = 1024; loc = b - 1024; }
    else if (b < 3072)  { in = W_ctx;            out = g_Wt_ctx; R = 1024; loc = b - 2048; }
    else if (b < 4096)  { in = W_in;             out = g_Wt_in;  R = 1024; loc = b - 3072; }
    else if (b < 7168)  { in = W_hh;             out = g_Wt_hh0; R = G3;   loc = b - 4096; }
    else if (b < 10240) { in = W_hh + G3 * 1024; out = g_Wt_hh1; R = G3;   loc = b - 7168; }
    else if (b < 13312) { in = W_ih;             out = g_Wt_ih0; R = G3;   loc = b - 10240; }
    else                { in = W_ih + G3 * 1024; out = g_Wt_ih1; R = G3;   loc = b - 13312; }
    int tr = loc >> 5;             // row tile index (over R)
    int tk = loc & 31;             // k tile index (over 1024)
    int x = threadIdx.x & 31, y = threadIdx.x >> 5;   // 32 x 8
#pragma unroll
    for (int i = 0; i < 4; i++) {
        int r = tr * 32 + y + i * 8;
        s[y + i * 8][x] = in[(size_t)r * 1024 + tk * 32 + x];
    }
    __syncthreads();
#pragma unroll
    for (int i = 0; i < 4; i++) {
        int k = tk * 32 + y + i * 8;
        out[(size_t)k * R + tr * 32 + x] = s[x][y + i * 8];
    }
}

// ---------------------------------------------------------------------------
// Prologue GEMM (64x64 tiles, K=1024), 512 blocks x 256 threads
//   mode 0: enc_proj   = enc_hids(2048x1024) @ Wt_enc
//   mode 1: emb_merged = emb[ids](2016x1024) @ Wt_in + b_in + b_ctx
// ---------------------------------------------------------------------------
__global__ void prol_gemm_kernel(int mode,
                                 const float* __restrict__ enc_hids,
                                 const int*   __restrict__ input_ids,
                                 const float* __restrict__ emb_table,
                                 const float* __restrict__ b_in,
                                 const float* __restrict__ b_ctx) {
    __shared__ float As[32 * 68];   // [k][row]
    __shared__ float Bs[32 * 64];   // [k][col]
    int b = blockIdx.x;
    int rt = b >> 4, ct = b & 15;
    int r0 = rt * 64, c0 = ct * 64;
    int tid = threadIdx.x;
    int tx = tid & 15, ty = tid >> 4;
    const float* Wt = (mode == 0) ? g_Wt_enc : g_Wt_in;
    int rows = (mode == 0) ? 2048 : (TSTEP * NB);

    float acc[4][4];
#pragma unroll
    for (int i = 0; i < 4; i++)
#pragma unroll
        for (int j = 0; j < 4; j++) acc[i][j] = 0.f;

    for (int k0 = 0; k0 < 1024; k0 += 32) {
        for (int idx = tid; idx < 64 * 32; idx += 256) {
            int r = idx >> 5, kk = idx & 31;
            int gr = r0 + r;
            float v = 0.f;
            if (mode == 0) {
                v = enc_hids[(size_t)gr * 1024 + k0 + kk];
            } else if (gr < rows) {
                int tt = gr >> 5, nn = gr & 31;
                int id = input_ids[nn * 64 + tt];
                v = emb_table[(size_t)id * 1024 + k0 + kk];
            }
            As[kk * 68 + r] = v;
        }
        for (int idx = tid; idx < 32 * 64; idx += 256) {
            int kk = idx >> 6, x = idx & 63;
            Bs[kk * 64 + x] = Wt[(size_t)(k0 + kk) * 1024 + c0 + x];
        }
        __syncthreads();
#pragma unroll
        for (int kk = 0; kk < 32; kk++) {
            float4 a4 = *(const float4*)&As[kk * 68 + ty * 4];
            float4 b4 = *(const float4*)&Bs[kk * 64 + tx * 4];
            float av[4] = {a4.x, a4.y, a4.z, a4.w};
            float bv[4] = {b4.x, b4.y, b4.z, b4.w};
#pragma unroll
            for (int i = 0; i < 4; i++)
#pragma unroll
                for (int j = 0; j < 4; j++) acc[i][j] += av[i] * bv[j];
        }
        __syncthreads();
    }
    float* out = (mode == 0) ? g_enc_proj : g_emb_merged;
#pragma unroll
    for (int i = 0; i < 4; i++) {
        int r = r0 + ty * 4 + i;
        if (r >= rows) continue;
#pragma unroll
        for (int j = 0; j < 4; j++) {
            int c = c0 + tx * 4 + j;
            float bias = (mode == 1) ? (b_in[c] + b_ctx[c]) : 0.f;
            out[(size_t)r * 1024 + c] = acc[i][j] + bias;
        }
    }
}

// ---------------------------------------------------------------------------
// Per-step GEMM core: out[32 x C] = A[32 x 1024] @ Wt[1024 x C] (+addend)
// block = 128 threads (4 warps x 4 cols = 16 cols per block); lane = batch n
// ---------------------------------------------------------------------------
__device__ __forceinline__ void gemm32_tile(const float* __restrict__ A,
                                            const float* __restrict__ Wt,
                                            int C, float* __restrict__ out,
                                            const float* __restrict__ addend,
                                            int tile, float* As) {
    int tid  = threadIdx.x;
    int w    = tid >> 5, lane = tid & 31;
    int jc   = tile * 16 + w * 4;
    float a0 = 0.f, a1 = 0.f, a2 = 0.f, a3 = 0.f;

    for (int k0 = 0; k0 < 1024; k0 += 128) {
        __syncthreads();
        for (int idx = tid; idx < 1024; idx += 128) {
            int n  = idx >> 5;       // 0..31
            int kq = idx & 31;       // quad within 128-k chunk
            float4 v = *(const float4*)(A + (size_t)n * 1024 + k0 + kq * 4);
            As[(kq * 4 + 0) * 33 + n] = v.x;
            As[(kq * 4 + 1) * 33 + n] = v.y;
            As[(kq * 4 + 2) * 33 + n] = v.z;
            As[(kq * 4 + 3) * 33 + n] = v.w;
        }
        __syncthreads();
        const float* wp = Wt + (size_t)k0 * C + jc;
#pragma unroll 8
        for (int kk = 0; kk < 128; kk++) {
            float  a  = As[kk * 33 + lane];
            float4 wv = *(const float4*)(wp + (size_t)kk * C);
            a0 += a * wv.x; a1 += a * wv.y; a2 += a * wv.z; a3 += a * wv.w;
        }
    }
    float4 r;
    if (addend) {
        const float4 ad = *(const float4*)(addend + (size_t)lane * C + jc);
        r.x = a0 + ad.x; r.y = a1 + ad.y; r.z = a2 + ad.z; r.w = a3 + ad.w;
    } else {
        r.x = a0; r.y = a1; r.z = a2; r.w = a3;
    }
    *(float4*)(out + (size_t)lane * C + jc) = r;
}

// phase A: dec_proj (64 tiles) + gh0 (192) + gh1 (192) = 448 blocks
__global__ void phaseA_kernel() {
    __shared__ float As[128 * 33];
    int b = blockIdx.x;
    if (b < 64)
        gemm32_tile(g_h + NB * HID, g_Wt_dec, 1024, g_dec_proj, nullptr, b, As);
    else if (b < 256)
        gemm32_tile(g_h,            g_Wt_hh0, G3,   g_gh0,      nullptr, b - 64, As);
    else
        gemm32_tile(g_h + NB * HID, g_Wt_hh1, G3,   g_gh1,      nullptr, b - 256, As);
}

// which: 0 = merged(ctx_proj + emb term), 1 = gi layer0, 2 = gi layer1
__global__ void gemm_single_kernel(int which, int t) {
    __shared__ float As[128 * 33];
    if (which == 0)
        gemm32_tile(g_ctx,    g_Wt_ctx, 1024, g_merged,
                    g_emb_merged + (size_t)t * NB * 1024, blockIdx.x, As);
    else if (which == 1)
        gemm32_tile(g_merged, g_Wt_ih0, G3, g_gi, nullptr, blockIdx.x, As);
    else
        gemm32_tile(g_h,      g_Wt_ih1, G3, g_gi, nullptr, blockIdx.x, As);
}

// ---------------------------------------------------------------------------
// Attention: score -> softmax -> ctx.  block per n (32 blocks, 256 threads)
// ---------------------------------------------------------------------------
__global__ void attn_kernel(const float* __restrict__ enc_hids,
                            const float* __restrict__ v_att,
                            float* __restrict__ out, int t) {
    __shared__ float sdec[1024];
    __shared__ float sv[1024];
    __shared__ float sscore[64];
    __shared__ float satt[64];
    int n = blockIdx.x, tid = threadIdx.x;
    for (int i = tid; i < 1024; i += 256) {
        sdec[i] = g_dec_proj[n * 1024 + i];
        sv[i]   = v_att[i];
    }
    __syncthreads();
    int w = tid >> 5, lane = tid & 31;
    for (int l = w; l < 64; l += 8) {
        const float* ep = g_enc_proj + ((size_t)n * 64 + l) * 1024;
        float s = 0.f;
        for (int a = lane; a < 1024; a += 32)
            s += tanhf(ep[a] + sdec[a]) * sv[a];
#pragma unroll
        for (int o = 16; o; o >>= 1) s += __shfl_xor_sync(0xffffffffu, s, o);
        if (lane == 0) sscore[l] = s;
    }
    __syncthreads();
    if (tid < 32) {
        float a0 = sscore[tid], a1 = sscore[tid + 32];
        float m = fmaxf(a0, a1);
#pragma unroll
        for (int o = 16; o; o >>= 1) m = fmaxf(m, __shfl_xor_sync(0xffffffffu, m, o));
        float e0 = expf(a0 - m), e1 = expf(a1 - m);
        float sum = e0 + e1;
#pragma unroll
        for (int o = 16; o; o >>= 1) sum += __shfl_xor_sync(0xffffffffu, sum, o);
        float inv = 1.f / sum;
        satt[tid]      = e0 * inv;
        satt[tid + 32] = e1 * inv;
        out[ATT_BASE + ((size_t)n * 64 + tid)      * TSTEP + t] = e0 * inv;
        out[ATT_BASE + ((size_t)n * 64 + tid + 32) * TSTEP + t] = e1 * inv;
    }
    __syncthreads();
    int d = tid * 4;
    float4 acc = {0.f, 0.f, 0.f, 0.f};
    const float* eh = enc_hids + (size_t)n * 64 * 1024 + d;
#pragma unroll 8
    for (int l = 0; l < 64; l++) {
        float  al = satt[l];
        float4 e  = *(const float4*)(eh + (size_t)l * 1024);
        acc.x += al * e.x; acc.y += al * e.y; acc.z += al * e.z; acc.w += al * e.w;
    }
    *(float4*)&g_ctx[n * 1024 + d] = acc;
}

// ---------------------------------------------------------------------------
// GRU combine: h_new = (1-z)*tanh(gi_n + r*gh_n') + z*h   (32 blocks x 256)
// ---------------------------------------------------------------------------
__device__ __forceinline__ float sigf(float x) { return 1.f / (1.f + expf(-x)); }

__global__ void combine_kernel(int layer, int t,
                               const float* __restrict__ b_ih_l,
                               const float* __restrict__ b_hh_l,
                               float* __restrict__ out_hid) {
    int n = blockIdx.x;
    int j = threadIdx.x * 4;
    const float* gi = g_gi + (size_t)n * G3;
    const float* gh = (layer ? g_gh1 : g_gh0) + (size_t)n * G3;
    float* h = g_h + (size_t)layer * NB * HID + n * HID;

    float4 gir = *(const float4*)(gi + j);
    float4 giz = *(const float4*)(gi + 1024 + j);
    float4 gin = *(const float4*)(gi + 2048 + j);
    float4 ghr = *(const float4*)(gh + j);
    float4 ghz = *(const float4*)(gh + 1024 + j);
    float4 ghn = *(const float4*)(gh + 2048 + j);
    float4 bir = *(const float4*)(b_ih_l + j);
    float4 biz = *(const float4*)(b_ih_l + 1024 + j);
    float4 bin = *(const float4*)(b_ih_l + 2048 + j);
    float4 bhr = *(const float4*)(b_hh_l + j);
    float4 bhz = *(const float4*)(b_hh_l + 1024 + j);
    float4 bhn = *(const float4*)(b_hh_l + 2048 + j);
    float4 ho  = *(const float4*)(h + j);

    float gir_[4] = {gir.x, gir.y, gir.z, gir.w}, giz_[4] = {giz.x, giz.y, giz.z, giz.w};
    float gin_[4] = {gin.x, gin.y, gin.z, gin.w}, ghr_[4] = {ghr.x, ghr.y, ghr.z, ghr.w};
    float ghz_[4] = {ghz.x, ghz.y, ghz.z, ghz.w}, ghn_[4] = {ghn.x, ghn.y, ghn.z, ghn.w};
    float bir_[4] = {bir.x, bir.y, bir.z, bir.w}, biz_[4] = {biz.x, biz.y, biz.z, biz.w};
    float bin_[4] = {bin.x, bin.y, bin.z, bin.w}, bhr_[4] = {bhr.x, bhr.y, bhr.z, bhr.w};
    float bhz_[4] = {bhz.x, bhz.y, bhz.z, bhz.w}, bhn_[4] = {bhn.x, bhn.y, bhn.z, bhn.w};
    float ho_[4]  = {ho.x, ho.y, ho.z, ho.w};
    float hn_[4];
#pragma unroll
    for (int c = 0; c < 4; c++) {
        float r  = sigf(gir_[c] + bir_[c] + ghr_[c] + bhr_[c]);
        float z  = sigf(giz_[c] + biz_[c] + ghz_[c] + bhz_[c]);
        float nn = tanhf(gin_[c] + bin_[c] + r * (ghn_[c] + bhn_[c]));
        hn_[c] = (1.f - z) * nn + z * ho_[c];
    }
    float4 hv = {hn_[0], hn_[1], hn_[2], hn_[3]};
    *(float4*)(h + j) = hv;
    if (out_hid)
        *(float4*)(out_hid + ((size_t)n * TSTEP + t) * 1024 + j) = hv;
}

// epilogue: final h stack -> dec_prev
__global__ void copy_hfinal_kernel(float* __restrict__ out) {
    int i = blockIdx.x * 256 + threadIdx.x;
    out[DECPREV_BASE + i] = g_h[i];
}

// ---------------------------------------------------------------------------
// Launch
// ---------------------------------------------------------------------------
extern "C" void kernel_launch(void* const* d_in, const int* in_sizes, int n_in,
                              void* d_out, int out_size) {
    const int*   input_ids = (const int*)  d_in[0];
    const float* dec_init  = (const float*)d_in[1];
    const float* enc_hids  = (const float*)d_in[2];
    const float* emb_table = (const float*)d_in[3];
    // W_in = d_in[4]
    const float* b_in      = (const float*)d_in[5];
    // W_ctx = d_in[6]
    const float* b_ctx     = (const float*)d_in[7];
    const float* W_att_dec = (const float*)d_in[8];
    const float* W_att_enc = (const float*)d_in[9];
    const float* v_att     = (const float*)d_in[10];
    const float* W_ih      = (const float*)d_in[11];
    const float* W_hh      = (const float*)d_in[12];
    const float* b_ih      = (const float*)d_in[13];
    const float* b_hh      = (const float*)d_in[14];
    const float* W_in      = (const float*)d_in[4];
    const float* W_ctx     = (const float*)d_in[6];
    float* out = (float*)d_out;

    init_h_kernel<<<256, 256>>>(dec_init);
    transpose_kernel<<<16384, 256>>>(W_att_dec, W_att_enc, W_ctx, W_in, W_hh, W_ih);
    prol_gemm_kernel<<<512, 256>>>(0, enc_hids, input_ids, emb_table, b_in, b_ctx);
    prol_gemm_kernel<<<512, 256>>>(1, enc_hids, input_ids, emb_table, b_in, b_ctx);

    for (int t = 0; t < TSTEP; t++) {
        phaseA_kernel<<<448, 128>>>();
        attn_kernel<<<32, 256>>>(enc_hids, v_att, out, t);
        gemm_single_kernel<<<64, 128>>>(0, t);       // merged
        gemm_single_kernel<<<192, 128>>>(1, t);      // gi layer0
        combine_kernel<<<32, 256>>>(0, t, b_ih, b_hh, nullptr);
        gemm_single_kernel<<<192, 128>>>(2, t);      // gi layer1
        combine_kernel<<<32, 256>>>(1, t, b_ih + G3, b_hh + G3, out);
    }
    copy_hfinal_kernel<<<256, 256>>>(out);
}

// round 3
// speedup vs baseline: 3.9757x; 3.9757x over previous
#include <cuda_runtime.h>
#include <cuda_bf16.h>
#include <math.h>

#define NB    32
#define HID   1024
#define TSTEP 63
#define ENCL  64
#define G3    3072

#define DEC_HIDS_ELEMS (NB * TSTEP * HID)
#define ATTS_ELEMS     (NB * ENCL * TSTEP)
#define ATT_BASE       DEC_HIDS_ELEMS
#define DECPREV_BASE   (DEC_HIDS_ELEMS + ATTS_ELEMS)

// ---------------------------------------------------------------------------
// Scratch
// ---------------------------------------------------------------------------
__device__ float g_enc_proj[NB * ENCL * 1024];     // [(n*64+l)][a]
__device__ float g_emb_merged[TSTEP * NB * 1024];  // emb@W_in^T + b_in + b_ctx

__device__ float g_h[2 * NB * HID];                // [layer][n][h]
__device__ float g_ctx[NB * HID];

__device__ float g_dp_part [2 * NB * HID];         // dec_proj partials
__device__ float g_gh0_part[2 * NB * G3];
__device__ float g_gh1_part[2 * NB * G3];
__device__ float g_mg_part [4 * NB * HID];         // ctx@W_ctx^T partials
__device__ float g_gi_part [4 * NB * G3];          // gi partials (reused l0/l1)

__device__ __forceinline__ float tanh_fast(float x) {
    float y;
    asm("tanh.approx.f32 %0, %1;" : "=f"(y) : "f"(x));
    return y;
}

// ---------------------------------------------------------------------------
__global__ void init_h_kernel(const float* __restrict__ dec_init) {
    int i = blockIdx.x * 256 + threadIdx.x;
    g_h[i] = dec_init[i];
}

// ---------------------------------------------------------------------------
// Per-step GEMM core: out_part[32 x C tile] = A[32 x KR@split] @ W[C x 1024]^T
// W in ORIGINAL [j][k] layout (k contiguous) -> coalesced loads.
// block = 256 threads; tile = 64 cols; k chunk = 32.
// amode 0: A = Aglob (32 x 1024 row-major)
// amode 1: A = emb_merged[t] + sum of 4 g_mg_part splits   (gi layer-0 input)
// ---------------------------------------------------------------------------
__device__ __forceinline__ void gemm_core(const float* __restrict__ Aglob,
                                          const float* __restrict__ W,
                                          int C, int tile, int split, int KR,
                                          float* __restrict__ outp,
                                          int amode, int t) {
    __shared__ float As[32 * 33];   // [k][n]
    __shared__ float Ws[32 * 68];   // [k][j]
    int tid = threadIdx.x;
    int j0 = tile * 64;
    int kbase = split * KR;
    int lp = tid & 7;           // float4 index within 32-k chunk
    int lr = tid >> 3;          // 0..31

    int tx = tid & 15;          // col quad
    int ty = tid >> 4;          // rows ty, ty+16
    float acc[2][4] = {{0.f,0.f,0.f,0.f},{0.f,0.f,0.f,0.f}};

    for (int kc = 0; kc < KR; kc += 32) {
        int k0 = kbase + kc;
        // stage A chunk (32n x 32k), transpose to As[k][n]
        float4 av;
        if (amode == 0) {
            av = *(const float4*)(Aglob + (size_t)lr * 1024 + k0 + lp * 4);
        } else {
            av = *(const float4*)(g_emb_merged + ((size_t)t * NB + lr) * 1024 + k0 + lp * 4);
#pragma unroll
            for (int s = 0; s < 4; s++) {
                float4 p = *(const float4*)(g_mg_part + ((size_t)s * NB + lr) * 1024 + k0 + lp * 4);
                av.x += p.x; av.y += p.y; av.z += p.z; av.w += p.w;
            }
        }
        As[(lp * 4 + 0) * 33 + lr] = av.x;
        As[(lp * 4 + 1) * 33 + lr] = av.y;
        As[(lp * 4 + 2) * 33 + lr] = av.z;
        As[(lp * 4 + 3) * 33 + lr] = av.w;
        // stage W chunk (64j x 32k), transpose to Ws[k][j]
#pragma unroll
        for (int h = 0; h < 2; h++) {
            int wj = lr + h * 32;
            float4 wv = *(const float4*)(W + (size_t)(j0 + wj) * 1024 + k0 + lp * 4);
            Ws[(lp * 4 + 0) * 68 + wj] = wv.x;
            Ws[(lp * 4 + 1) * 68 + wj] = wv.y;
            Ws[(lp * 4 + 2) * 68 + wj] = wv.z;
            Ws[(lp * 4 + 3) * 68 + wj] = wv.w;
        }
        __syncthreads();
#pragma unroll
        for (int kk = 0; kk < 32; kk++) {
            float a0 = As[kk * 33 + ty];
            float a1 = As[kk * 33 + ty + 16];
            float4 w4 = *(const float4*)&Ws[kk * 68 + tx * 4];
            acc[0][0] += a0 * w4.x; acc[0][1] += a0 * w4.y;
            acc[0][2] += a0 * w4.z; acc[0][3] += a0 * w4.w;
            acc[1][0] += a1 * w4.x; acc[1][1] += a1 * w4.y;
            acc[1][2] += a1 * w4.z; acc[1][3] += a1 * w4.w;
        }
        __syncthreads();
    }
#pragma unroll
    for (int i = 0; i < 2; i++) {
        int n = ty + i * 16;
        float4 r = {acc[i][0], acc[i][1], acc[i][2], acc[i][3]};
        *(float4*)(outp + (size_t)n * C + j0 + tx * 4) = r;
    }
}

// phase A: dec_proj(16 tiles x2) + gh0(48x2) + gh1(48x2) = 224 blocks
__global__ void phaseA_kernel(const float* __restrict__ W_att_dec,
                              const float* __restrict__ W_hh) {
    int b = blockIdx.x;
    if (b < 32) {
        int tile = b >> 1, split = b & 1;
        gemm_core(g_h + NB * HID, W_att_dec, 1024, tile, split, 512,
                  g_dp_part + (size_t)split * NB * 1024, 0, 0);
    } else if (b < 128) {
        int x = b - 32; int tile = x >> 1, split = x & 1;
        gemm_core(g_h, W_hh, G3, tile, split, 512,
                  g_gh0_part + (size_t)split * NB * G3, 0, 0);
    } else {
        int x = b - 128; int tile = x >> 1, split = x & 1;
        gemm_core(g_h + NB * HID, W_hh + (size_t)G3 * 1024, G3, tile, split, 512,
                  g_gh1_part + (size_t)split * NB * G3, 0, 0);
    }
}

// merged partials: ctx @ W_ctx^T ; 16 tiles x 4 splits = 64 blocks
__global__ void merged_kernel(const float* __restrict__ W_ctx) {
    int tile = blockIdx.x >> 2, split = blockIdx.x & 3;
    gemm_core(g_ctx, W_ctx, 1024, tile, split, 256,
              g_mg_part + (size_t)split * NB * 1024, 0, 0);
}

// gi: 48 tiles x 4 splits = 192 blocks. layer0: A = merged (amode 1); layer1: A = h0
__global__ void gi_kernel(int layer, int t, const float* __restrict__ W_ih) {
    int tile = blockIdx.x % 48, split = blockIdx.x / 48;
    const float* W = W_ih + (size_t)layer * G3 * 1024;
    if (layer == 0)
        gemm_core(nullptr, W, G3, tile, split, 256,
                  g_gi_part + (size_t)split * NB * G3, 1, t);
    else
        gemm_core(g_h, W, G3, tile, split, 256,
                  g_gi_part + (size_t)split * NB * G3, 0, 0);
}

// ---------------------------------------------------------------------------
// Prologue GEMM (64x64 tiles, K=1024): mode 0 enc_proj, mode 1 emb_merged
// ---------------------------------------------------------------------------
__global__ void prol_gemm_kernel(int mode,
                                 const float* __restrict__ enc_hids,
                                 const int*   __restrict__ input_ids,
                                 const float* __restrict__ emb_table,
                                 const float* __restrict__ b_in,
                                 const float* __restrict__ b_ctx,
                                 const float* __restrict__ W) {
    __shared__ float As[32 * 68];   // [k][r]
    __shared__ float Ws[32 * 68];   // [k][j]
    int b = blockIdx.x;
    int rt = b >> 4, ct = b & 15;
    int r0 = rt * 64, c0 = ct * 64;
    int tid = threadIdx.x;
    int lp = tid & 7, lr = tid >> 3;
    int tx = tid & 15, ty = tid >> 4;
    int rows = (mode == 0) ? 2048 : (TSTEP * NB);

    float acc[4][4];
#pragma unroll
    for (int i = 0; i < 4; i++)
#pragma unroll
        for (int j = 0; j < 4; j++) acc[i][j] = 0.f;

    for (int k0 = 0; k0 < 1024; k0 += 32) {
#pragma unroll
        for (int h = 0; h < 2; h++) {
            int r = lr + h * 32;
            int gr = r0 + r;
            float4 v = {0.f, 0.f, 0.f, 0.f};
            if (mode == 0) {
                v = *(const float4*)(enc_hids + (size_t)gr * 1024 + k0 + lp * 4);
            } else if (gr < rows) {
                int tt = gr >> 5, nn = gr & 31;
                int id = input_ids[nn * 64 + tt];
                v = *(const float4*)(emb_table + (size_t)id * 1024 + k0 + lp * 4);
            }
            As[(lp * 4 + 0) * 68 + r] = v.x;
            As[(lp * 4 + 1) * 68 + r] = v.y;
            As[(lp * 4 + 2) * 68 + r] = v.z;
            As[(lp * 4 + 3) * 68 + r] = v.w;
            int wj = r;
            float4 wv = *(const float4*)(W + (size_t)(c0 + wj) * 1024 + k0 + lp * 4);
            Ws[(lp * 4 + 0) * 68 + wj] = wv.x;
            Ws[(lp * 4 + 1) * 68 + wj] = wv.y;
            Ws[(lp * 4 + 2) * 68 + wj] = wv.z;
            Ws[(lp * 4 + 3) * 68 + wj] = wv.w;
        }
        __syncthreads();
#pragma unroll
        for (int kk = 0; kk < 32; kk++) {
            float4 a4 = *(const float4*)&As[kk * 68 + ty * 4];
            float4 b4 = *(const float4*)&Ws[kk * 68 + tx * 4];
            float av[4] = {a4.x, a4.y, a4.z, a4.w};
            float bv[4] = {b4.x, b4.y, b4.z, b4.w};
#pragma unroll
            for (int i = 0; i < 4; i++)
#pragma unroll
                for (int j = 0; j < 4; j++) acc[i][j] += av[i] * bv[j];
        }
        __syncthreads();
    }
    float* out = (mode == 0) ? g_enc_proj : g_emb_merged;
#pragma unroll
    for (int i = 0; i < 4; i++) {
        int r = r0 + ty * 4 + i;
        if (r >= rows) continue;
#pragma unroll
        for (int j = 0; j < 4; j++) {
            int c = c0 + tx * 4 + j;
            float bias = (mode == 1) ? (b_in[c] + b_ctx[c]) : 0.f;
            out[(size_t)r * 1024 + c] = acc[i][j] + bias;
        }
    }
}

// ---------------------------------------------------------------------------
// Attention (block per n): score(tanh.approx) -> softmax -> ctx
// ---------------------------------------------------------------------------
__global__ void attn_kernel(const float* __restrict__ enc_hids,
                            const float* __restrict__ v_att,
                            float* __restrict__ out, int t) {
    __shared__ float sdec[1024];
    __shared__ float sv[1024];
    __shared__ float sscore[64];
    __shared__ float satt[64];
    int n = blockIdx.x, tid = threadIdx.x;
    for (int i = tid; i < 1024; i += 256) {
        sdec[i] = g_dp_part[n * 1024 + i] + g_dp_part[NB * 1024 + n * 1024 + i];
        sv[i]   = v_att[i];
    }
    __syncthreads();
    int w = tid >> 5, lane = tid & 31;
    for (int l = w; l < 64; l += 8) {
        const float* ep = g_enc_proj + ((size_t)n * 64 + l) * 1024;
        float s = 0.f;
        for (int a = lane; a < 1024; a += 32)
            s += tanh_fast(ep[a] + sdec[a]) * sv[a];
#pragma unroll
        for (int o = 16; o; o >>= 1) s += __shfl_xor_sync(0xffffffffu, s, o);
        if (lane == 0) sscore[l] = s;
    }
    __syncthreads();
    if (tid < 32) {
        float a0 = sscore[tid], a1 = sscore[tid + 32];
        float m = fmaxf(a0, a1);
#pragma unroll
        for (int o = 16; o; o >>= 1) m = fmaxf(m, __shfl_xor_sync(0xffffffffu, m, o));
        float e0 = __expf(a0 - m), e1 = __expf(a1 - m);
        float sum = e0 + e1;
#pragma unroll
        for (int o = 16; o; o >>= 1) sum += __shfl_xor_sync(0xffffffffu, sum, o);
        float inv = 1.f / sum;
        satt[tid]      = e0 * inv;
        satt[tid + 32] = e1 * inv;
        out[ATT_BASE + ((size_t)n * 64 + tid)      * TSTEP + t] = e0 * inv;
        out[ATT_BASE + ((size_t)n * 64 + tid + 32) * TSTEP + t] = e1 * inv;
    }
    __syncthreads();
    int d = tid * 4;
    float4 acc = {0.f, 0.f, 0.f, 0.f};
    const float* eh = enc_hids + (size_t)n * 64 * 1024 + d;
#pragma unroll 8
    for (int l = 0; l < 64; l++) {
        float  al = satt[l];
        float4 e  = *(const float4*)(eh + (size_t)l * 1024);
        acc.x += al * e.x; acc.y += al * e.y; acc.z += al * e.z; acc.w += al * e.w;
    }
    *(float4*)&g_ctx[n * 1024 + d] = acc;
}

// ---------------------------------------------------------------------------
// GRU combine: sums 4 gi partials + 2 gh partials + biases, updates h
// ---------------------------------------------------------------------------
__device__ __forceinline__ void add4(float* a, float4 v) {
    a[0] += v.x; a[1] += v.y; a[2] += v.z; a[3] += v.w;
}

__global__ void combine_kernel(int layer, int t,
                               const float* __restrict__ b_ih_l,
                               const float* __restrict__ b_hh_l,
                               float* __restrict__ out_hid) {
    int n = blockIdx.x;
    int j = threadIdx.x * 4;
    const float* ghp = layer ? g_gh1_part : g_gh0_part;
    float* h = g_h + (size_t)layer * NB * HID + n * HID;

    float gi[3][4] = {}, gh[3][4] = {};
#pragma unroll
    for (int g = 0; g < 3; g++) {
#pragma unroll
        for (int s = 0; s < 4; s++)
            add4(gi[g], *(const float4*)(g_gi_part + ((size_t)s * NB + n) * G3 + g * 1024 + j));
#pragma unroll
        for (int s = 0; s < 2; s++)
            add4(gh[g], *(const float4*)(ghp + ((size_t)s * NB + n) * G3 + g * 1024 + j));
        add4(gi[g], *(const float4*)(b_ih_l + g * 1024 + j));
        add4(gh[g], *(const float4*)(b_hh_l + g * 1024 + j));
    }
    float4 ho = *(const float4*)(h + j);
    float ho_[4] = {ho.x, ho.y, ho.z, ho.w};
    float hn_[4];
#pragma unroll
    for (int c = 0; c < 4; c++) {
        float r  = 1.f / (1.f + expf(-(gi[0][c] + gh[0][c])));
        float z  = 1.f / (1.f + expf(-(gi[1][c] + gh[1][c])));
        float nn = tanhf(gi[2][c] + r * gh[2][c]);
        hn_[c] = (1.f - z) * nn + z * ho_[c];
    }
    float4 hv = {hn_[0], hn_[1], hn_[2], hn_[3]};
    *(float4*)(h + j) = hv;
    if (out_hid)
        *(float4*)(out_hid + ((size_t)n * TSTEP + t) * 1024 + j) = hv;
}

__global__ void copy_hfinal_kernel(float* __restrict__ out) {
    int i = blockIdx.x * 256 + threadIdx.x;
    out[DECPREV_BASE + i] = g_h[i];
}

// ---------------------------------------------------------------------------
extern "C" void kernel_launch(void* const* d_in, const int* in_sizes, int n_in,
                              void* d_out, int out_size) {
    const int*   input_ids = (const int*)  d_in[0];
    const float* dec_init  = (const float*)d_in[1];
    const float* enc_hids  = (const float*)d_in[2];
    const float* emb_table = (const float*)d_in[3];
    const float* W_in      = (const float*)d_in[4];
    const float* b_in      = (const float*)d_in[5];
    const float* W_ctx     = (const float*)d_in[6];
    const float* b_ctx     = (const float*)d_in[7];
    const float* W_att_dec = (const float*)d_in[8];
    const float* W_att_enc = (const float*)d_in[9];
    const float* v_att     = (const float*)d_in[10];
    const float* W_ih      = (const float*)d_in[11];
    const float* W_hh      = (const float*)d_in[12];
    const float* b_ih      = (const float*)d_in[13];
    const float* b_hh      = (const float*)d_in[14];
    float* out = (float*)d_out;

    init_h_kernel<<<256, 256>>>(dec_init);
    prol_gemm_kernel<<<512, 256>>>(0, enc_hids, input_ids, emb_table, b_in, b_ctx, W_att_enc);
    prol_gemm_kernel<<<512, 256>>>(1, enc_hids, input_ids, emb_table, b_in, b_ctx, W_in);

    for (int t = 0; t < TSTEP; t++) {
        phaseA_kernel<<<224, 256>>>(W_att_dec, W_hh);
        attn_kernel<<<32, 256>>>(enc_hids, v_att, out, t);
        merged_kernel<<<64, 256>>>(W_ctx);
        gi_kernel<<<192, 256>>>(0, t, W_ih);
        combine_kernel<<<32, 256>>>(0, t, b_ih, b_hh, nullptr);
        gi_kernel<<<192, 256>>>(1, t, W_ih);
        combine_kernel<<<32, 256>>>(1, t, b_ih + G3, b_hh + G3, out);
    }
    copy_hfinal_kernel<<<256, 256>>>(out);
}

// round 4
// speedup vs baseline: 4.5518x; 1.1449x over previous
#include <cuda_runtime.h>
#include <cuda_bf16.h>
#include <math.h>

#define NB    32
#define HID   1024
#define TSTEP 63
#define ENCL  64
#define G3    3072

#define DEC_HIDS_ELEMS (NB * TSTEP * HID)
#define ATTS_ELEMS     (NB * ENCL * TSTEP)
#define ATT_BASE       DEC_HIDS_ELEMS
#define DECPREV_BASE   (DEC_HIDS_ELEMS + ATTS_ELEMS)

// ---------------------------------------------------------------------------
// Scratch
// ---------------------------------------------------------------------------
__device__ float g_enc_proj[NB * ENCL * 1024];
__device__ float g_emb_merged[TSTEP * NB * 1024];

__device__ float g_h[2 * NB * HID];
__device__ float g_ctx[NB * HID];
__device__ float g_score[NB * ENCL];

__device__ float g_dp_part [4 * NB * HID];
__device__ float g_gh0_part[4 * NB * G3];
__device__ float g_gh1_part[4 * NB * G3];
__device__ float g_mg_part [4 * NB * HID];
__device__ float g_gi_part [4 * NB * G3];

__device__ __forceinline__ float tanh_fast(float x) {
    float y;
    asm("tanh.approx.f32 %0, %1;" : "=f"(y) : "f"(x));
    return y;
}

__global__ void init_h_kernel(const float* __restrict__ dec_init) {
    int i = blockIdx.x * 256 + threadIdx.x;
    g_h[i] = dec_init[i];
}

// ---------------------------------------------------------------------------
// Per-step GEMM: out[32 x 64-col tile] = A[32 x KR] @ W[C x 1024]^T, split-K
// Double-buffered smem staging with register prefetch.
// amode 0: A = Aglob; amode 1: A = emb_merged[t] + 4 mg partials
// ---------------------------------------------------------------------------
__device__ __forceinline__ void gemm_fetch(const float* __restrict__ Aglob,
                                           const float* __restrict__ W,
                                           int j0, int k0, int amode, int t,
                                           int lp, int lr,
                                           float4& av, float4& w0, float4& w1) {
    if (amode == 0) {
        av = *(const float4*)(Aglob + (size_t)lr * 1024 + k0 + lp * 4);
    } else {
        av = *(const float4*)(g_emb_merged + ((size_t)t * NB + lr) * 1024 + k0 + lp * 4);
#pragma unroll
        for (int s = 0; s < 4; s++) {
            float4 p = *(const float4*)(g_mg_part + ((size_t)s * NB + lr) * 1024 + k0 + lp * 4);
            av.x += p.x; av.y += p.y; av.z += p.z; av.w += p.w;
        }
    }
    w0 = *(const float4*)(W + (size_t)(j0 + lr)      * 1024 + k0 + lp * 4);
    w1 = *(const float4*)(W + (size_t)(j0 + lr + 32) * 1024 + k0 + lp * 4);
}

__device__ __forceinline__ void gemm_store(float* __restrict__ As,
                                           float* __restrict__ Ws,
                                           int lp, int lr,
                                           float4 av, float4 w0, float4 w1) {
    As[(lp * 4 + 0) * 33 + lr] = av.x;
    As[(lp * 4 + 1) * 33 + lr] = av.y;
    As[(lp * 4 + 2) * 33 + lr] = av.z;
    As[(lp * 4 + 3) * 33 + lr] = av.w;
    Ws[(lp * 4 + 0) * 68 + lr] = w0.x;
    Ws[(lp * 4 + 1) * 68 + lr] = w0.y;
    Ws[(lp * 4 + 2) * 68 + lr] = w0.z;
    Ws[(lp * 4 + 3) * 68 + lr] = w0.w;
    Ws[(lp * 4 + 0) * 68 + lr + 32] = w1.x;
    Ws[(lp * 4 + 1) * 68 + lr + 32] = w1.y;
    Ws[(lp * 4 + 2) * 68 + lr + 32] = w1.z;
    Ws[(lp * 4 + 3) * 68 + lr + 32] = w1.w;
}

__device__ __forceinline__ void gemm_core(const float* __restrict__ Aglob,
                                          const float* __restrict__ W,
                                          int C, int tile, int split, int KR,
                                          float* __restrict__ outp,
                                          int amode, int t) {
    __shared__ float As[2][32 * 33];
    __shared__ float Ws[2][32 * 68];
    int tid = threadIdx.x;
    int j0 = tile * 64;
    int kbase = split * KR;
    int lp = tid & 7, lr = tid >> 3;
    int tx = tid & 15, ty = tid >> 4;

    float4 av, w0, w1;
    gemm_fetch(Aglob, W, j0, kbase, amode, t, lp, lr, av, w0, w1);
    gemm_store(As[0], Ws[0], lp, lr, av, w0, w1);
    __syncthreads();

    float acc[2][4] = {{0.f,0.f,0.f,0.f},{0.f,0.f,0.f,0.f}};
    int nch = KR / 32;
    for (int c = 0; c < nch; c++) {
        const float* as = As[c & 1];
        const float* ws = Ws[c & 1];
        if (c + 1 < nch)
            gemm_fetch(Aglob, W, j0, kbase + (c + 1) * 32, amode, t, lp, lr, av, w0, w1);
#pragma unroll
        for (int kk = 0; kk < 32; kk++) {
            float a0 = as[kk * 33 + ty];
            float a1 = as[kk * 33 + ty + 16];
            float4 w4 = *(const float4*)&ws[kk * 68 + tx * 4];
            acc[0][0] += a0 * w4.x; acc[0][1] += a0 * w4.y;
            acc[0][2] += a0 * w4.z; acc[0][3] += a0 * w4.w;
            acc[1][0] += a1 * w4.x; acc[1][1] += a1 * w4.y;
            acc[1][2] += a1 * w4.z; acc[1][3] += a1 * w4.w;
        }
        if (c + 1 < nch) {
            gemm_store(As[(c + 1) & 1], Ws[(c + 1) & 1], lp, lr, av, w0, w1);
            __syncthreads();
        }
    }
#pragma unroll
    for (int i = 0; i < 2; i++) {
        int n = ty + i * 16;
        float4 r = {acc[i][0], acc[i][1], acc[i][2], acc[i][3]};
        *(float4*)(outp + (size_t)n * C + j0 + tx * 4) = r;
    }
}

// phase A: dec_proj(16 tiles x4) + gh0(48x4) + gh1(48x4) = 448 blocks, KR=256
__global__ void phaseA_kernel(const float* __restrict__ W_att_dec,
                              const float* __restrict__ W_hh) {
    int b = blockIdx.x;
    if (b < 64) {
        int tile = b >> 2, split = b & 3;
        gemm_core(g_h + NB * HID, W_att_dec, 1024, tile, split, 256,
                  g_dp_part + (size_t)split * NB * 1024, 0, 0);
    } else if (b < 256) {
        int x = b - 64; int tile = x >> 2, split = x & 3;
        gemm_core(g_h, W_hh, G3, tile, split, 256,
                  g_gh0_part + (size_t)split * NB * G3, 0, 0);
    } else {
        int x = b - 256; int tile = x >> 2, split = x & 3;
        gemm_core(g_h + NB * HID, W_hh + (size_t)G3 * 1024, G3, tile, split, 256,
                  g_gh1_part + (size_t)split * NB * G3, 0, 0);
    }
}

__global__ void merged_kernel(const float* __restrict__ W_ctx) {
    int tile = blockIdx.x >> 2, split = blockIdx.x & 3;
    gemm_core(g_ctx, W_ctx, 1024, tile, split, 256,
              g_mg_part + (size_t)split * NB * 1024, 0, 0);
}

__global__ void gi_kernel(int layer, int t, const float* __restrict__ W_ih) {
    int tile = blockIdx.x % 48, split = blockIdx.x / 48;
    const float* W = W_ih + (size_t)layer * G3 * 1024;
    if (layer == 0)
        gemm_core(nullptr, W, G3, tile, split, 256,
                  g_gi_part + (size_t)split * NB * G3, 1, t);
    else
        gemm_core(g_h, W, G3, tile, split, 256,
                  g_gi_part + (size_t)split * NB * G3, 0, 0);
}

// ---------------------------------------------------------------------------
// Prologue GEMM (64x64 tiles, K=1024), double-buffered
// mode 0: enc_proj = enc_hids @ W_att_enc^T ; mode 1: emb_merged
// ---------------------------------------------------------------------------
__global__ void prol_gemm_kernel(int mode,
                                 const float* __restrict__ enc_hids,
                                 const int*   __restrict__ input_ids,
                                 const float* __restrict__ emb_table,
                                 const float* __restrict__ b_in,
                                 const float* __restrict__ b_ctx,
                                 const float* __restrict__ W) {
    __shared__ float As[2][32 * 68];
    __shared__ float Ws[2][32 * 68];
    int b = blockIdx.x;
    int rt = b >> 4, ct = b & 15;
    int r0 = rt * 64, c0 = ct * 64;
    int tid = threadIdx.x;
    int lp = tid & 7, lr = tid >> 3;
    int tx = tid & 15, ty = tid >> 4;
    int rows = (mode == 0) ? 2048 : (TSTEP * NB);

    float4 a[2], wv[2];
#define PROL_FETCH(k0)                                                          \
    {                                                                           \
        _Pragma("unroll")                                                       \
        for (int h = 0; h < 2; h++) {                                           \
            int gr = r0 + lr + h * 32;                                          \
            if (mode == 0) {                                                    \
                a[h] = *(const float4*)(enc_hids + (size_t)gr * 1024 + (k0) + lp * 4); \
            } else if (gr < rows) {                                             \
                int id = input_ids[(gr & 31) * 64 + (gr >> 5)];                 \
                a[h] = *(const float4*)(emb_table + (size_t)id * 1024 + (k0) + lp * 4); \
            } else {                                                            \
                a[h] = make_float4(0.f, 0.f, 0.f, 0.f);                         \
            }                                                                   \
            wv[h] = *(const float4*)(W + (size_t)(c0 + lr + h * 32) * 1024 + (k0) + lp * 4); \
        }                                                                       \
    }
#define PROL_STORE(buf)                                                         \
    {                                                                           \
        _Pragma("unroll")                                                       \
        for (int h = 0; h < 2; h++) {                                           \
            int r = lr + h * 32;                                                \
            As[buf][(lp * 4 + 0) * 68 + r] = a[h].x;                            \
            As[buf][(lp * 4 + 1) * 68 + r] = a[h].y;                            \
            As[buf][(lp * 4 + 2) * 68 + r] = a[h].z;                            \
            As[buf][(lp * 4 + 3) * 68 + r] = a[h].w;                            \
            Ws[buf][(lp * 4 + 0) * 68 + r] = wv[h].x;                           \
            Ws[buf][(lp * 4 + 1) * 68 + r] = wv[h].y;                           \
            Ws[buf][(lp * 4 + 2) * 68 + r] = wv[h].z;                           \
            Ws[buf][(lp * 4 + 3) * 68 + r] = wv[h].w;                           \
        }                                                                       \
    }

    float acc[4][4];
#pragma unroll
    for (int i = 0; i < 4; i++)
#pragma unroll
        for (int j = 0; j < 4; j++) acc[i][j] = 0.f;

    PROL_FETCH(0);
    PROL_STORE(0);
    __syncthreads();
    for (int c = 0; c < 32; c++) {
        const float* as = As[c & 1];
        const float* ws = Ws[c & 1];
        if (c + 1 < 32) PROL_FETCH((c + 1) * 32);
#pragma unroll
        for (int kk = 0; kk < 32; kk++) {
            float4 a4 = *(const float4*)&as[kk * 68 + ty * 4];
            float4 b4 = *(const float4*)&ws[kk * 68 + tx * 4];
            float avv[4] = {a4.x, a4.y, a4.z, a4.w};
            float bvv[4] = {b4.x, b4.y, b4.z, b4.w};
#pragma unroll
            for (int i = 0; i < 4; i++)
#pragma unroll
                for (int j = 0; j < 4; j++) acc[i][j] += avv[i] * bvv[j];
        }
        if (c + 1 < 32) {
            PROL_STORE((c + 1) & 1);
            __syncthreads();
        }
    }
    float* outb = (mode == 0) ? g_enc_proj : g_emb_merged;
#pragma unroll
    for (int i = 0; i < 4; i++) {
        int r = r0 + ty * 4 + i;
        if (r >= rows) continue;
#pragma unroll
        for (int j = 0; j < 4; j++) {
            int c = c0 + tx * 4 + j;
            float bias = (mode == 1) ? (b_in[c] + b_ctx[c]) : 0.f;
            outb[(size_t)r * 1024 + c] = acc[i][j] + bias;
        }
    }
#undef PROL_FETCH
#undef PROL_STORE
}

// ---------------------------------------------------------------------------
// Attention scores: 256 blocks (n x 8 l-groups), 128 threads; tanh.approx
// ---------------------------------------------------------------------------
__global__ void score_kernel(const float* __restrict__ v_att) {
    __shared__ float sdec[1024];
    __shared__ float sv[1024];
    int b = blockIdx.x;
    int n = b >> 3, lg = b & 7;
    int tid = threadIdx.x;
    for (int i = tid; i < 1024; i += 128) {
        sdec[i] = g_dp_part[n * 1024 + i]
                + g_dp_part[(NB + n) * 1024 + i]
                + g_dp_part[(2 * NB + n) * 1024 + i]
                + g_dp_part[(3 * NB + n) * 1024 + i];
        sv[i] = v_att[i];
    }
    __syncthreads();
    int w = tid >> 5, lane = tid & 31;
#pragma unroll
    for (int li = 0; li < 2; li++) {
        int l = lg * 8 + w * 2 + li;
        const float* ep = g_enc_proj + ((size_t)n * 64 + l) * 1024;
        float s = 0.f;
        for (int a = lane; a < 1024; a += 32)
            s += tanh_fast(ep[a] + sdec[a]) * sv[a];
#pragma unroll
        for (int o = 16; o; o >>= 1) s += __shfl_xor_sync(0xffffffffu, s, o);
        if (lane == 0) g_score[n * 64 + l] = s;
    }
}

// softmax + atts output + ctx (32 blocks, 256 threads)
__global__ void softctx_kernel(const float* __restrict__ enc_hids,
                               float* __restrict__ out, int t) {
    __shared__ float satt[64];
    int n = blockIdx.x, tid = threadIdx.x;
    if (tid < 32) {
        float a0 = g_score[n * 64 + tid], a1 = g_score[n * 64 + tid + 32];
        float m = fmaxf(a0, a1);
#pragma unroll
        for (int o = 16; o; o >>= 1) m = fmaxf(m, __shfl_xor_sync(0xffffffffu, m, o));
        float e0 = __expf(a0 - m), e1 = __expf(a1 - m);
        float sum = e0 + e1;
#pragma unroll
        for (int o = 16; o; o >>= 1) sum += __shfl_xor_sync(0xffffffffu, sum, o);
        float inv = 1.f / sum;
        satt[tid]      = e0 * inv;
        satt[tid + 32] = e1 * inv;
        out[ATT_BASE + ((size_t)n * 64 + tid)      * TSTEP + t] = e0 * inv;
        out[ATT_BASE + ((size_t)n * 64 + tid + 32) * TSTEP + t] = e1 * inv;
    }
    __syncthreads();
    int d = tid * 4;
    float4 acc = {0.f, 0.f, 0.f, 0.f};
    const float* eh = enc_hids + (size_t)n * 64 * 1024 + d;
#pragma unroll 8
    for (int l = 0; l < 64; l++) {
        float  al = satt[l];
        float4 e  = *(const float4*)(eh + (size_t)l * 1024);
        acc.x += al * e.x; acc.y += al * e.y; acc.z += al * e.z; acc.w += al * e.w;
    }
    *(float4*)&g_ctx[n * 1024 + d] = acc;
}

// ---------------------------------------------------------------------------
// GRU combine: sums 4 gi + 4 gh partials + biases, updates h
// ---------------------------------------------------------------------------
__device__ __forceinline__ void add4(float* a, float4 v) {
    a[0] += v.x; a[1] += v.y; a[2] += v.z; a[3] += v.w;
}

__global__ void combine_kernel(int layer, int t,
                               const float* __restrict__ b_ih_l,
                               const float* __restrict__ b_hh_l,
                               float* __restrict__ out_hid) {
    int n = blockIdx.x;
    int j = threadIdx.x * 4;
    const float* ghp = layer ? g_gh1_part : g_gh0_part;
    float* h = g_h + (size_t)layer * NB * HID + n * HID;

    float gi[3][4] = {}, gh[3][4] = {};
#pragma unroll
    for (int g = 0; g < 3; g++) {
#pragma unroll
        for (int s = 0; s < 4; s++) {
            add4(gi[g], *(const float4*)(g_gi_part + ((size_t)s * NB + n) * G3 + g * 1024 + j));
            add4(gh[g], *(const float4*)(ghp       + ((size_t)s * NB + n) * G3 + g * 1024 + j));
        }
        add4(gi[g], *(const float4*)(b_ih_l + g * 1024 + j));
        add4(gh[g], *(const float4*)(b_hh_l + g * 1024 + j));
    }
    float4 ho = *(const float4*)(h + j);
    float ho_[4] = {ho.x, ho.y, ho.z, ho.w};
    float hn_[4];
#pragma unroll
    for (int c = 0; c < 4; c++) {
        float r  = 1.f / (1.f + expf(-(gi[0][c] + gh[0][c])));
        float z  = 1.f / (1.f + expf(-(gi[1][c] + gh[1][c])));
        float nn = tanhf(gi[2][c] + r * gh[2][c]);
        hn_[c] = (1.f - z) * nn + z * ho_[c];
    }
    float4 hv = {hn_[0], hn_[1], hn_[2], hn_[3]};
    *(float4*)(h + j) = hv;
    if (out_hid)
        *(float4*)(out_hid + ((size_t)n * TSTEP + t) * 1024 + j) = hv;
}

__global__ void copy_hfinal_kernel(float* __restrict__ out) {
    int i = blockIdx.x * 256 + threadIdx.x;
    out[DECPREV_BASE + i] = g_h[i];
}

// ---------------------------------------------------------------------------
extern "C" void kernel_launch(void* const* d_in, const int* in_sizes, int n_in,
                              void* d_out, int out_size) {
    const int*   input_ids = (const int*)  d_in[0];
    const float* dec_init  = (const float*)d_in[1];
    const float* enc_hids  = (const float*)d_in[2];
    const float* emb_table = (const float*)d_in[3];
    const float* W_in      = (const float*)d_in[4];
    const float* b_in      = (const float*)d_in[5];
    const float* W_ctx     = (const float*)d_in[6];
    const float* b_ctx     = (const float*)d_in[7];
    const float* W_att_dec = (const float*)d_in[8];
    const float* W_att_enc = (const float*)d_in[9];
    const float* v_att     = (const float*)d_in[10];
    const float* W_ih      = (const float*)d_in[11];
    const float* W_hh      = (const float*)d_in[12];
    const float* b_ih      = (const float*)d_in[13];
    const float* b_hh      = (const float*)d_in[14];
    float* out = (float*)d_out;

    init_h_kernel<<<256, 256>>>(dec_init);
    prol_gemm_kernel<<<512, 256>>>(0, enc_hids, input_ids, emb_table, b_in, b_ctx, W_att_enc);
    prol_gemm_kernel<<<512, 256>>>(1, enc_hids, input_ids, emb_table, b_in, b_ctx, W_in);

    for (int t = 0; t < TSTEP; t++) {
        phaseA_kernel<<<448, 256>>>(W_att_dec, W_hh);
        score_kernel<<<256, 128>>>(v_att);
        softctx_kernel<<<32, 256>>>(enc_hids, out, t);
        merged_kernel<<<64, 256>>>(W_ctx);
        gi_kernel<<<192, 256>>>(0, t, W_ih);
        combine_kernel<<<32, 256>>>(0, t, b_ih, b_hh, nullptr);
        gi_kernel<<<192, 256>>>(1, t, W_ih);
        combine_kernel<<<32, 256>>>(1, t, b_ih + G3, b_hh + G3, out);
    }
    copy_hfinal_kernel<<<256, 256>>>(out);
}